// round 2
// baseline (speedup 1.0000x reference)
#include <cuda_runtime.h>
#include <math.h>

#define CH 28
#define CP 32          // padded channel count for 128B-aligned corners
#define INV_SQ8 0.35355339059327373f

// Scratch (allocation-free contract: __device__ globals)
__device__ float g_vol1[CH * 32 * 32 * 32];          //  3.5 MB
__device__ float g_vol2[CH * 64 * 64 * 64];          //   28 MB
__device__ float g_volF[128 * 128 * 128 * CP];       //  268 MB, (z,y,x,c) channel-last

// ---------------------------------------------------------------------------
// One level of inverse 3D Haar, channel-major output (C, 2D, 2D, 2D).
// Thread per (c,i,j,k): read the 8 subband coeffs once, write 8 outputs
// as four float2 stores (r=0,1 contiguous).
// Subband order s = u*4 + v*2 + w; sign = (-1)^(u*p + v*q + w*r).
// ---------------------------------------------------------------------------
template <int D>
__global__ void idwt_small(const float* __restrict__ approx,
                           const float* __restrict__ det,
                           float* __restrict__ out) {
    const int vol = CH * D * D * D;
    int idx = blockIdx.x * blockDim.x + threadIdx.x;
    if (idx >= vol) return;
    int k = idx % D;
    int j = (idx / D) % D;
    int i = (idx / (D * D)) % D;
    int c = idx / (D * D * D);

    float a[8];
    a[0] = approx[idx];
#pragma unroll
    for (int s = 1; s < 8; s++) a[s] = det[(size_t)(s - 1) * vol + idx];

    const int R = 2 * D;
    size_t base = (((size_t)c * R + 2 * i) * R + 2 * j) * R + 2 * k;
#pragma unroll
    for (int p = 0; p < 2; p++)
#pragma unroll
        for (int q = 0; q < 2; q++) {
            float b0 = 0.f, b1 = 0.f;
#pragma unroll
            for (int u = 0; u < 2; u++)
#pragma unroll
                for (int v = 0; v < 2; v++) {
                    float sgn = ((u & p) ^ (v & q)) ? -1.f : 1.f;
                    b0 += sgn * a[u * 4 + v * 2 + 0];
                    b1 += sgn * a[u * 4 + v * 2 + 1];
                }
            float2 val = make_float2(INV_SQ8 * (b0 + b1), INV_SQ8 * (b0 - b1));
            *(float2*)(out + base + ((size_t)p * R + q) * R) = val;
        }
}

// ---------------------------------------------------------------------------
// Final IDWT level (D=64 -> R=128) fused with transpose to channel-last
// padded layout (z, y, x, CP). Block = 256 threads = 32 channels x 8 k's,
// handling one (i, j) coarse pair and a k-tile of 8. Shared-memory staging
// gives fully coalesced 512-float output bursts per (p,q) octant.
// ---------------------------------------------------------------------------
__global__ void idwt_final(const float* __restrict__ approx,
                           const float* __restrict__ det,
                           float* __restrict__ out) {
    const int D = 64, R = 128;
    const int vol = CH * D * D * D;
    int bid = blockIdx.x;
    int ktile = bid & 7;
    int j = (bid >> 3) & 63;
    int i = bid >> 9;
    int k0 = ktile * 8;

    int tid = threadIdx.x;
    int c  = tid >> 3;   // 0..31 (28..31 are zero pad lanes)
    int kl = tid & 7;    // 0..7

    __shared__ float sh[4][16][CP + 1];

    float o[4][2];
    if (c < CH) {
        int idx = ((c * D + i) * D + j) * D + k0 + kl;
        float a[8];
        a[0] = approx[idx];
#pragma unroll
        for (int s = 1; s < 8; s++) a[s] = det[(size_t)(s - 1) * vol + idx];
#pragma unroll
        for (int p = 0; p < 2; p++)
#pragma unroll
            for (int q = 0; q < 2; q++) {
                float b0 = 0.f, b1 = 0.f;
#pragma unroll
                for (int u = 0; u < 2; u++)
#pragma unroll
                    for (int v = 0; v < 2; v++) {
                        float sgn = ((u & p) ^ (v & q)) ? -1.f : 1.f;
                        b0 += sgn * a[u * 4 + v * 2 + 0];
                        b1 += sgn * a[u * 4 + v * 2 + 1];
                    }
                o[p * 2 + q][0] = INV_SQ8 * (b0 + b1);
                o[p * 2 + q][1] = INV_SQ8 * (b0 - b1);
            }
    } else {
#pragma unroll
        for (int pq = 0; pq < 4; pq++) { o[pq][0] = 0.f; o[pq][1] = 0.f; }
    }

#pragma unroll
    for (int pq = 0; pq < 4; pq++) {
        sh[pq][2 * kl + 0][c] = o[pq][0];
        sh[pq][2 * kl + 1][c] = o[pq][1];
    }
    __syncthreads();

#pragma unroll
    for (int pq = 0; pq < 4; pq++) {
        int p = pq >> 1, q = pq & 1;
        size_t base = (((size_t)(2 * i + p) * R + (2 * j + q)) * R + 2 * k0) * CP;
        out[base + tid]       = sh[pq][tid >> 5][tid & 31];
        out[base + 256 + tid] = sh[pq][(tid >> 5) + 8][tid & 31];
    }
}

// ---------------------------------------------------------------------------
// Trilinear query: one warp per point, lane = channel. Each corner is one
// 128B-aligned contiguous block (channel-last padded volume) -> 8 fully
// coalesced 4-sector loads per point; coalesced 112B output store.
// Inputs are guaranteed in [-1.5, 1.5) so all 8 corners are in-bounds.
// ---------------------------------------------------------------------------
__global__ void query_kernel(const float* __restrict__ xyz,
                             const float* __restrict__ vol,
                             float* __restrict__ out, int N) {
    int gw = (blockIdx.x * blockDim.x + threadIdx.x) >> 5;
    int lane = threadIdx.x & 31;
    if (gw >= N) return;

    float x = xyz[3 * gw + 0];
    float y = xyz[3 * gw + 1];
    float z = xyz[3 * gw + 2];

    const float half127 = 0.5f * 127.0f;
    float px = (x / 1.5f + 1.0f) * half127;
    float py = (y / 1.5f + 1.0f) * half127;
    float pz = (z / 1.5f + 1.0f) * half127;

    float flx = floorf(px), fly = floorf(py), flz = floorf(pz);
    float fx = px - flx, fy = py - fly, fz = pz - flz;
    int x0 = min(max((int)flx, 0), 126);
    int y0 = min(max((int)fly, 0), 126);
    int z0 = min(max((int)flz, 0), 126);

    float wx1 = fx, wx0 = 1.f - fx;
    float wy1 = fy, wy0 = 1.f - fy;
    float wz1 = fz, wz0 = 1.f - fz;

    if (lane >= CH) return;

    size_t b = (((size_t)z0 * 128 + y0) * 128 + x0) * CP + lane;
    const size_t DX = CP, DY = (size_t)128 * CP, DZ = (size_t)128 * 128 * CP;

    float v000 = vol[b];
    float v001 = vol[b + DX];
    float v010 = vol[b + DY];
    float v011 = vol[b + DY + DX];
    float v100 = vol[b + DZ];
    float v101 = vol[b + DZ + DX];
    float v110 = vol[b + DZ + DY];
    float v111 = vol[b + DZ + DY + DX];

    float v = wz0 * (wy0 * (wx0 * v000 + wx1 * v001) +
                     wy1 * (wx0 * v010 + wx1 * v011)) +
              wz1 * (wy0 * (wx0 * v100 + wx1 * v101) +
                     wy1 * (wx0 * v110 + wx1 * v111));

    out[(size_t)gw * CH + lane] = v;
}

extern "C" void kernel_launch(void* const* d_in, const int* in_sizes, int n_in,
                              void* d_out, int out_size) {
    const float* approx = (const float*)d_in[0];   // (28,16,16,16)
    const float* det0   = (const float*)d_in[1];   // (7,28,16,16,16)
    const float* det1   = (const float*)d_in[2];   // (7,28,32,32,32)
    const float* det2   = (const float*)d_in[3];   // (7,28,64,64,64)
    const float* xyz    = (const float*)d_in[4];   // (N,3)
    int N = in_sizes[4] / 3;

    float *vol1, *vol2, *volF;
    cudaGetSymbolAddress((void**)&vol1, g_vol1);
    cudaGetSymbolAddress((void**)&vol2, g_vol2);
    cudaGetSymbolAddress((void**)&volF, g_volF);

    {   // level 0: 16 -> 32
        int n = CH * 16 * 16 * 16;
        idwt_small<16><<<(n + 255) / 256, 256>>>(approx, det0, vol1);
    }
    {   // level 1: 32 -> 64
        int n = CH * 32 * 32 * 32;
        idwt_small<32><<<(n + 255) / 256, 256>>>(vol1, det1, vol2);
    }
    // level 2: 64 -> 128, fused transpose to (z,y,x,32)
    idwt_final<<<64 * 64 * 8, 256>>>(vol2, det2, volF);

    // trilinear gather, one warp per point
    query_kernel<<<(N + 7) / 8, 256>>>(xyz, volF, (float*)d_out, N);
}